// round 9
// baseline (speedup 1.0000x reference)
#include <cuda_runtime.h>
#include <cuda_bf16.h>
#include <math.h>
#include <stdint.h>

// Problem shapes (fixed per reference)
#define PB 2048
#define PS 32
#define PD 1024
#define PH 1024
#define PM 4096
#define PK 32

// ===================== low-level helpers ====================================
__device__ __forceinline__ uint32_t smem_to_u32(const void* p) {
    uint32_t a;
    asm("{ .reg .u64 t; cvta.to.shared.u64 t, %1; cvt.u32.u64 %0, t; }" : "=r"(a) : "l"(p));
    return a;
}
__device__ __forceinline__ void ldsm_x4(uint32_t* r, uint32_t addr) {
    asm volatile("ldmatrix.sync.aligned.m8n8.x4.shared.b16 {%0,%1,%2,%3}, [%4];"
                 : "=r"(r[0]), "=r"(r[1]), "=r"(r[2]), "=r"(r[3]) : "r"(addr));
}
__device__ __forceinline__ void mma_bf16(float* d, const uint32_t* a, const uint32_t* b) {
    asm volatile(
        "mma.sync.aligned.m16n8k16.row.col.f32.bf16.bf16.f32 "
        "{%0,%1,%2,%3}, {%4,%5,%6,%7}, {%8,%9}, {%0,%1,%2,%3};\n"
        : "+f"(d[0]), "+f"(d[1]), "+f"(d[2]), "+f"(d[3])
        : "r"(a[0]), "r"(a[1]), "r"(a[2]), "r"(a[3]), "r"(b[0]), "r"(b[1]));
}
__device__ __forceinline__ void mma_u8s8(int32_t* d, const uint32_t* a, const uint32_t* b) {
    asm volatile(
        "mma.sync.aligned.m16n8k32.row.col.s32.u8.s8.s32 "
        "{%0,%1,%2,%3}, {%4,%5,%6,%7}, {%8,%9}, {%0,%1,%2,%3};\n"
        : "+r"(d[0]), "+r"(d[1]), "+r"(d[2]), "+r"(d[3])
        : "r"(a[0]), "r"(a[1]), "r"(a[2]), "r"(a[3]), "r"(b[0]), "r"(b[1]));
}
__device__ __forceinline__ void cpasync16(uint32_t s, const void* g) {
    asm volatile("cp.async.cg.shared.global [%0], [%1], 16;" :: "r"(s), "l"(g));
}
__device__ __forceinline__ void cp_commit() {
    asm volatile("cp.async.commit_group;" ::: "memory");
}

// ===================== scratch (device globals) =============================
__device__ float g_query[(size_t)PB * PH];
__device__ float g_sim[(size_t)PB * PM];
__device__ float g_act[(size_t)PB * PM];
__device__ float g_gate[PB];
__device__ float g_vals[PB * PK];
__device__ int   g_idx[PB * PK];

__device__ __nv_bfloat16 g_xh[(size_t)PB * PS * PD];
__device__ __nv_bfloat16 g_xl[(size_t)PB * PS * PD];
__device__ __nv_bfloat16 g_qh[(size_t)PB * PH];
__device__ __nv_bfloat16 g_ql[(size_t)PB * PH];
__device__ __nv_bfloat16 g_rh[(size_t)PB * PH];
__device__ __nv_bfloat16 g_rl[(size_t)PB * PH];

__device__ uint8_t g_prob8[(size_t)PB * PM];           // u8, prob*255
__device__ int8_t  g_assoc8[(size_t)PM * PM];          // s8, assoc^T*1024, [N][K]

__device__ __nv_bfloat16 g_wencT_h[(size_t)PH * PD];
__device__ __nv_bfloat16 g_wencT_l[(size_t)PH * PD];
__device__ __nv_bfloat16 g_wdecT_h[(size_t)PD * PH];
__device__ __nv_bfloat16 g_wdecT_l[(size_t)PD * PH];
__device__ __nv_bfloat16 g_memT_h[(size_t)PM * PH];
__device__ __nv_bfloat16 g_memT_l[(size_t)PM * PH];

// ===================== bf16 hi/lo split helpers =============================
__device__ __forceinline__ void split4(float4 v, uint2& hi, uint2& lo) {
    __nv_bfloat16 h0 = __float2bfloat16_rn(v.x);
    __nv_bfloat16 h1 = __float2bfloat16_rn(v.y);
    __nv_bfloat16 h2 = __float2bfloat16_rn(v.z);
    __nv_bfloat16 h3 = __float2bfloat16_rn(v.w);
    __nv_bfloat16 l0 = __float2bfloat16_rn(v.x - __bfloat162float(h0));
    __nv_bfloat16 l1 = __float2bfloat16_rn(v.y - __bfloat162float(h1));
    __nv_bfloat16 l2 = __float2bfloat16_rn(v.z - __bfloat162float(h2));
    __nv_bfloat16 l3 = __float2bfloat16_rn(v.w - __bfloat162float(h3));
    hi.x = (uint32_t)__bfloat16_as_ushort(h0) | ((uint32_t)__bfloat16_as_ushort(h1) << 16);
    hi.y = (uint32_t)__bfloat16_as_ushort(h2) | ((uint32_t)__bfloat16_as_ushort(h3) << 16);
    lo.x = (uint32_t)__bfloat16_as_ushort(l0) | ((uint32_t)__bfloat16_as_ushort(l1) << 16);
    lo.y = (uint32_t)__bfloat16_as_ushort(l2) | ((uint32_t)__bfloat16_as_ushort(l3) << 16);
}

// ===================== prep kernels =========================================
// in [K][N] fp32 row-major -> out hi/lo [N][K] bf16 (transpose + split)
__global__ __launch_bounds__(256)
void transpose_split_kernel(const float* __restrict__ in, __nv_bfloat16* __restrict__ oh,
                            __nv_bfloat16* __restrict__ ol, int K, int N)
{
    __shared__ float t[32][33];
    const int tx = threadIdx.x & 31, ty = threadIdx.x >> 5;
    const int n_base = blockIdx.x * 32, k_base = blockIdx.y * 32;
#pragma unroll
    for (int j = 0; j < 4; j++) {
        int k = k_base + ty + j * 8;
        t[ty + j * 8][tx] = __ldcs(in + (size_t)k * N + n_base + tx);
    }
    __syncthreads();
#pragma unroll
    for (int j = 0; j < 4; j++) {
        int n = n_base + ty + j * 8;
        int k = k_base + tx;
        float v = t[tx][ty + j * 8];
        __nv_bfloat16 h = __float2bfloat16_rn(v);
        __nv_bfloat16 l = __float2bfloat16_rn(v - __bfloat162float(h));
        oh[(size_t)n * K + k] = h;
        ol[(size_t)n * K + k] = l;
    }
}

// in [K][N] fp32 -> out [N][K] s8 scaled by 1024 (clamped +-127)
__global__ __launch_bounds__(256)
void transpose_i8_kernel(const float* __restrict__ in, int8_t* __restrict__ o8,
                         int K, int N)
{
    __shared__ float t[32][33];
    const int tx = threadIdx.x & 31, ty = threadIdx.x >> 5;
    const int n_base = blockIdx.x * 32, k_base = blockIdx.y * 32;
#pragma unroll
    for (int j = 0; j < 4; j++) {
        int k = k_base + ty + j * 8;
        t[ty + j * 8][tx] = __ldcs(in + (size_t)k * N + n_base + tx);
    }
    __syncthreads();
#pragma unroll
    for (int j = 0; j < 4; j++) {
        int n = n_base + ty + j * 8;
        int k = k_base + tx;
        float v = t[tx][ty + j * 8] * 1024.0f;
        int q = __float2int_rn(fmaxf(fminf(v, 127.0f), -127.0f));
        o8[(size_t)n * K + k] = (int8_t)q;
    }
}

// elementwise fp32 -> bf16 hi/lo
__global__ __launch_bounds__(256)
void split_kernel(const float* __restrict__ in, __nv_bfloat16* __restrict__ oh,
                  __nv_bfloat16* __restrict__ ol)
{
    const size_t i = (size_t)blockIdx.x * 256 + threadIdx.x;
    float4 v = __ldcs((const float4*)in + i);
    uint2 hi, lo;
    split4(v, hi, lo);
    __stcs((uint2*)oh + i, hi);
    __stcs((uint2*)ol + i, lo);
}

// ===================== bf16 tensor-core GEMM (split3) =======================
// C[M,N] = (Ah+Al)[M,K] * (Bh+Bl)^T   all row-major bf16 [rows][K]
// Tile 128x128, BK=32, 256 thr (8 warps x 64x32), 2-stage cp.async pipeline.
// EPI 0: C fp32
// EPI 1: out[b][s][n] = tanh(c + bias[n]) broadcast over s (decoder+bcast)
// EPI 2: per-32-row-group mean of tanh(c+bias) -> Qf fp32 + Qh/Ql bf16
#define GPAD 80u
#define OPSZ 10240u                 // 128 rows * 80 B

template <int EPI>
__global__ __launch_bounds__(256, 2)
void gemm_cp(const __nv_bfloat16* __restrict__ Ah, const __nv_bfloat16* __restrict__ Al,
             const __nv_bfloat16* __restrict__ Bh, const __nv_bfloat16* __restrict__ Bl,
             const float* __restrict__ bias, float* __restrict__ C,
             float* __restrict__ Qf, __nv_bfloat16* __restrict__ Qh,
             __nv_bfloat16* __restrict__ Ql, int M, int N, int K)
{
    extern __shared__ char sm[];
    const uint32_t smb = smem_to_u32(sm);
    const int tid = threadIdx.x, wid = tid >> 5, lane = tid & 31;
    const int m0 = blockIdx.y * 128, n0 = blockIdx.x * 128;
    const int wm = (wid >> 2) * 64, wn = (wid & 3) * 32;
    const uint32_t offB = 2u * OPSZ;
    const uint32_t STG = 4u * OPSZ;

    float acc[4][4][4];
#pragma unroll
    for (int i = 0; i < 4; i++)
#pragma unroll
        for (int j = 0; j < 4; j++)
#pragma unroll
            for (int q = 0; q < 4; q++) acc[i][j][q] = 0.f;

    const int c_row0 = tid >> 2, c_ch0 = (tid & 3);
    const int c_row1 = (tid + 256) >> 2, c_ch1 = ((tid + 256) & 3);

    const int lr = lane & 15;
    const int kh = (lane >> 4) ? 8 : 0;
    const int br = (lane & 7) + ((lane & 16) ? 8 : 0);
    const int bk = (lane & 8) ? 8 : 0;

    const int nch = K >> 5;

#define ISSUE(cc, bb) do {                                                         \
    const int _k0 = (cc) << 5;                                                     \
    const uint32_t _sb = smb + (bb) * STG;                                         \
    cpasync16(_sb + c_row0 * GPAD + c_ch0 * 16,                                    \
              Ah + (size_t)(m0 + c_row0) * K + _k0 + c_ch0 * 8);                   \
    cpasync16(_sb + c_row1 * GPAD + c_ch1 * 16,                                    \
              Ah + (size_t)(m0 + c_row1) * K + _k0 + c_ch1 * 8);                   \
    cpasync16(_sb + offB + c_row0 * GPAD + c_ch0 * 16,                             \
              Bh + (size_t)(n0 + c_row0) * K + _k0 + c_ch0 * 8);                   \
    cpasync16(_sb + offB + c_row1 * GPAD + c_ch1 * 16,                             \
              Bh + (size_t)(n0 + c_row1) * K + _k0 + c_ch1 * 8);                   \
    cpasync16(_sb + OPSZ + c_row0 * GPAD + c_ch0 * 16,                             \
              Al + (size_t)(m0 + c_row0) * K + _k0 + c_ch0 * 8);                   \
    cpasync16(_sb + OPSZ + c_row1 * GPAD + c_ch1 * 16,                             \
              Al + (size_t)(m0 + c_row1) * K + _k0 + c_ch1 * 8);                   \
    cpasync16(_sb + 3u * OPSZ + c_row0 * GPAD + c_ch0 * 16,                        \
              Bl + (size_t)(n0 + c_row0) * K + _k0 + c_ch0 * 8);                   \
    cpasync16(_sb + 3u * OPSZ + c_row1 * GPAD + c_ch1 * 16,                        \
              Bl + (size_t)(n0 + c_row1) * K + _k0 + c_ch1 * 8);                   \
    cp_commit();                                                                   \
} while (0)

    ISSUE(0, 0);

    for (int c = 0; c < nch; c++) {
        const int buf = c & 1;
        if (c + 1 < nch) {
            ISSUE(c + 1, buf ^ 1);
            asm volatile("cp.async.wait_group 1;" ::: "memory");
        } else {
            asm volatile("cp.async.wait_group 0;" ::: "memory");
        }
        __syncthreads();

        const uint32_t sb = smb + buf * STG;
#pragma unroll
        for (int ks = 0; ks < 2; ks++) {
            uint32_t ah[4][4], bhf[2][4];
#pragma unroll
            for (int mt = 0; mt < 4; mt++)
                ldsm_x4(ah[mt], sb + (wm + mt * 16 + lr) * GPAD + (ks * 16 + kh) * 2);
#pragma unroll
            for (int p = 0; p < 2; p++)
                ldsm_x4(bhf[p], sb + offB + (wn + p * 16 + br) * GPAD + (ks * 16 + bk) * 2);
#pragma unroll
            for (int mt = 0; mt < 4; mt++)
#pragma unroll
                for (int nt = 0; nt < 4; nt++)
                    mma_bf16(acc[mt][nt], ah[mt], &bhf[nt >> 1][(nt & 1) * 2]);
            {
                uint32_t al[4][4];
#pragma unroll
                for (int mt = 0; mt < 4; mt++)
                    ldsm_x4(al[mt], sb + OPSZ + (wm + mt * 16 + lr) * GPAD + (ks * 16 + kh) * 2);
#pragma unroll
                for (int mt = 0; mt < 4; mt++)
#pragma unroll
                    for (int nt = 0; nt < 4; nt++)
                        mma_bf16(acc[mt][nt], al[mt], &bhf[nt >> 1][(nt & 1) * 2]);
                uint32_t blf[2][4];
#pragma unroll
                for (int p = 0; p < 2; p++)
                    ldsm_x4(blf[p], sb + 3u * OPSZ + (wn + p * 16 + br) * GPAD + (ks * 16 + bk) * 2);
#pragma unroll
                for (int mt = 0; mt < 4; mt++)
#pragma unroll
                    for (int nt = 0; nt < 4; nt++)
                        mma_bf16(acc[mt][nt], ah[mt], &blf[nt >> 1][(nt & 1) * 2]);
            }
        }
        __syncthreads();
    }
#undef ISSUE

    // -------- epilogue: regs -> smem (padded) -> gmem -----------------------
    float* smf = (float*)sm;   // 128 x 132 floats = 67584 B
#pragma unroll
    for (int mt = 0; mt < 4; mt++) {
#pragma unroll
        for (int nt = 0; nt < 4; nt++) {
            int r = wm + mt * 16 + (lane >> 2);
            int cc = wn + nt * 8 + (lane & 3) * 2;
            float v0 = acc[mt][nt][0], v1 = acc[mt][nt][1];
            float v2 = acc[mt][nt][2], v3 = acc[mt][nt][3];
            if (EPI >= 1) {
                float b0 = bias[n0 + cc], b1 = bias[n0 + cc + 1];
                v0 = tanhf(v0 + b0); v1 = tanhf(v1 + b1);
                v2 = tanhf(v2 + b0); v3 = tanhf(v3 + b1);
            }
            smf[r * 132 + cc] = v0;
            smf[r * 132 + cc + 1] = v1;
            smf[(r + 8) * 132 + cc] = v2;
            smf[(r + 8) * 132 + cc + 1] = v3;
        }
    }
    __syncthreads();

    if (EPI == 2) {
#pragma unroll
        for (int i = 0; i < 2; i++) {
            int task = tid + i * 256;           // 512: 4 groups x 128 cols
            int grp = task >> 7, col = task & 127;
            float s = 0.f;
#pragma unroll
            for (int rr = 0; rr < 32; rr++) s += smf[(grp * 32 + rr) * 132 + col];
            s *= (1.0f / 32.0f);
            size_t qi = (size_t)(blockIdx.y * 4 + grp) * N + n0 + col;
            Qf[qi] = s;
            __nv_bfloat16 h = __float2bfloat16_rn(s);
            __nv_bfloat16 l = __float2bfloat16_rn(s - __bfloat162float(h));
            Qh[qi] = h;
            Ql[qi] = l;
        }
    } else if (EPI == 1) {
        // decoder + broadcast: row = batch b, write to out[b][s][:] for all s
#pragma unroll
        for (int i = 0; i < 16; i++) {
            int id = tid + i * 256;
            int row = id >> 5, c4 = id & 31;
            float4 o;
            o.x = smf[row * 132 + c4 * 4 + 0];
            o.y = smf[row * 132 + c4 * 4 + 1];
            o.z = smf[row * 132 + c4 * 4 + 2];
            o.w = smf[row * 132 + c4 * 4 + 3];
            float* base = C + ((size_t)(m0 + row) * PS) * PD + n0 + c4 * 4;
            for (int s = 0; s < PS; s++)
                __stcs((float4*)(base + (size_t)s * PD), o);
        }
    } else {
#pragma unroll
        for (int i = 0; i < 16; i++) {
            int id = tid + i * 256;
            int row = id >> 5, c4 = id & 31;
            float4 o;
            o.x = smf[row * 132 + c4 * 4 + 0];
            o.y = smf[row * 132 + c4 * 4 + 1];
            o.z = smf[row * 132 + c4 * 4 + 2];
            o.w = smf[row * 132 + c4 * 4 + 3];
            *(float4*)(C + (size_t)(m0 + row) * N + n0 + c4 * 4) = o;
        }
    }
}

// ===================== int8 tensor-core GEMM (assoc) ========================
// C[M,N] = (A*255)[M,K]u8 * ((B*1024)[N][K]s8)^T / (255*1024)
// Tile 128x128, BK=64 bytes, 2-stage cp.async, m16n8k32 u8.s8 IMMA.
__global__ __launch_bounds__(256, 2)
void gemm_i8(const uint8_t* __restrict__ A, const int8_t* __restrict__ B,
             float* __restrict__ C, int M, int N, int K)
{
    extern __shared__ char sm[];
    const uint32_t smb = smem_to_u32(sm);
    const int tid = threadIdx.x, wid = tid >> 5, lane = tid & 31;
    const int m0 = blockIdx.y * 128, n0 = blockIdx.x * 128;
    const int wm = (wid >> 2) * 64, wn = (wid & 3) * 32;
    const uint32_t offB = OPSZ;
    const uint32_t STG = 2u * OPSZ;

    int32_t acc[4][4][4];
#pragma unroll
    for (int i = 0; i < 4; i++)
#pragma unroll
        for (int j = 0; j < 4; j++)
#pragma unroll
            for (int q = 0; q < 4; q++) acc[i][j][q] = 0;

    const int c_row0 = tid >> 2, c_ch0 = (tid & 3);
    const int c_row1 = (tid + 256) >> 2, c_ch1 = ((tid + 256) & 3);

    const int lr = lane & 15;
    const int khb = (lane >> 4) ? 16 : 0;                 // byte offset within 32B k-step
    const int br = (lane & 7) + ((lane & 16) ? 8 : 0);
    const int bkb = (lane & 8) ? 16 : 0;

    const int nch = K >> 6;                               // 64 int8 per chunk

#define ISSUE8(cc, bb) do {                                                        \
    const int _k0 = (cc) << 6;                                                     \
    const uint32_t _sb = smb + (bb) * STG;                                         \
    cpasync16(_sb + c_row0 * GPAD + c_ch0 * 16,                                    \
              A + (size_t)(m0 + c_row0) * K + _k0 + c_ch0 * 16);                   \
    cpasync16(_sb + c_row1 * GPAD + c_ch1 * 16,                                    \
              A + (size_t)(m0 + c_row1) * K + _k0 + c_ch1 * 16);                   \
    cpasync16(_sb + offB + c_row0 * GPAD + c_ch0 * 16,                             \
              B + (size_t)(n0 + c_row0) * K + _k0 + c_ch0 * 16);                   \
    cpasync16(_sb + offB + c_row1 * GPAD + c_ch1 * 16,                             \
              B + (size_t)(n0 + c_row1) * K + _k0 + c_ch1 * 16);                   \
    cp_commit();                                                                   \
} while (0)

    ISSUE8(0, 0);

    for (int c = 0; c < nch; c++) {
        const int buf = c & 1;
        if (c + 1 < nch) {
            ISSUE8(c + 1, buf ^ 1);
            asm volatile("cp.async.wait_group 1;" ::: "memory");
        } else {
            asm volatile("cp.async.wait_group 0;" ::: "memory");
        }
        __syncthreads();

        const uint32_t sb = smb + buf * STG;
#pragma unroll
        for (int ks = 0; ks < 2; ks++) {                  // 2 x 32-byte k-steps
            uint32_t ah[4][4], bhf[2][4];
#pragma unroll
            for (int mt = 0; mt < 4; mt++)
                ldsm_x4(ah[mt], sb + (wm + mt * 16 + lr) * GPAD + ks * 32 + khb);
#pragma unroll
            for (int p = 0; p < 2; p++)
                ldsm_x4(bhf[p], sb + offB + (wn + p * 16 + br) * GPAD + ks * 32 + bkb);
#pragma unroll
            for (int mt = 0; mt < 4; mt++)
#pragma unroll
                for (int nt = 0; nt < 4; nt++)
                    mma_u8s8(acc[mt][nt], ah[mt], &bhf[nt >> 1][(nt & 1) * 2]);
        }
        __syncthreads();
    }
#undef ISSUE8

    // epilogue with descale
    float* smf = (float*)sm;
    const float DS = 1.0f / (255.0f * 1024.0f);
#pragma unroll
    for (int mt = 0; mt < 4; mt++) {
#pragma unroll
        for (int nt = 0; nt < 4; nt++) {
            int r = wm + mt * 16 + (lane >> 2);
            int cc = wn + nt * 8 + (lane & 3) * 2;
            smf[r * 132 + cc]           = (float)acc[mt][nt][0] * DS;
            smf[r * 132 + cc + 1]       = (float)acc[mt][nt][1] * DS;
            smf[(r + 8) * 132 + cc]     = (float)acc[mt][nt][2] * DS;
            smf[(r + 8) * 132 + cc + 1] = (float)acc[mt][nt][3] * DS;
        }
    }
    __syncthreads();
#pragma unroll
    for (int i = 0; i < 16; i++) {
        int id = tid + i * 256;
        int row = id >> 5, c4 = id & 31;
        float4 o;
        o.x = smf[row * 132 + c4 * 4 + 0];
        o.y = smf[row * 132 + c4 * 4 + 1];
        o.z = smf[row * 132 + c4 * 4 + 2];
        o.w = smf[row * 132 + c4 * 4 + 3];
        *(float4*)(C + (size_t)(m0 + row) * N + n0 + c4 * 4) = o;
    }
}

// ===================== small kernels =======================================
__global__ __launch_bounds__(256)
void gate_kernel(const float* __restrict__ query, const float* __restrict__ w_curv,
                 const float* __restrict__ b_curv, float* __restrict__ gate)
{
    const int b = blockIdx.x;
    const int tid = threadIdx.x;
    float s = 0.f;
    for (int h = tid; h < PH; h += 256) s += query[(size_t)b * PH + h] * w_curv[h];
    __shared__ float red[256];
    red[tid] = s;
    __syncthreads();
    for (int off = 128; off > 0; off >>= 1) {
        if (tid < off) red[tid] += red[tid + off];
        __syncthreads();
    }
    if (tid == 0) {
        float z = red[0] + b_curv[0];
        gate[b] = 1.f / (1.f + expf(-z));
    }
}

// register-resident iterative top-32
__global__ __launch_bounds__(256)
void topk_kernel(const float* __restrict__ sim, float* __restrict__ vals,
                 int* __restrict__ idx)
{
    const int b = blockIdx.x, tid = threadIdx.x, lane = tid & 31, wid = tid >> 5;
    const float* row = sim + (size_t)b * PM;
    float v[16];
#pragma unroll
    for (int i = 0; i < 16; i++) v[i] = row[tid + i * 256];
    float lm = -INFINITY; int ls = 0;
#pragma unroll
    for (int i = 0; i < 16; i++) if (v[i] > lm) { lm = v[i]; ls = i; }

    __shared__ float swv[8];
    __shared__ int   swi[8];
    __shared__ int   sbest;

    for (int k = 0; k < PK; k++) {
        float m = lm; int mi = ls * 256 + tid;
#pragma unroll
        for (int o = 16; o > 0; o >>= 1) {
            float ov = __shfl_xor_sync(0xffffffffu, m, o);
            int   oi = __shfl_xor_sync(0xffffffffu, mi, o);
            if (ov > m || (ov == m && oi < mi)) { m = ov; mi = oi; }
        }
        if (lane == 0) { swv[wid] = m; swi[wid] = mi; }
        __syncthreads();
        if (tid == 0) {
            float bv = swv[0]; int bi = swi[0];
#pragma unroll
            for (int w = 1; w < 8; w++)
                if (swv[w] > bv || (swv[w] == bv && swi[w] < bi)) { bv = swv[w]; bi = swi[w]; }
            vals[b * PK + k] = bv;
            idx[b * PK + k]  = bi;
            sbest = bi;
        }
        __syncthreads();
        const int bi = sbest;
        if ((bi & 255) == tid) {
            const int slot = bi >> 8;
#pragma unroll
            for (int i = 0; i < 16; i++) if (i == slot) v[i] = -INFINITY;
            lm = -INFINITY; ls = 0;
#pragma unroll
            for (int i = 0; i < 16; i++) if (v[i] > lm) { lm = v[i]; ls = i; }
        }
    }
}

// row softmax over M=4096, writes u8 scaled by 255 (IMMA-ready A operand)
__global__ __launch_bounds__(256)
void softmax_kernel(const float* __restrict__ in, uint8_t* __restrict__ out)
{
    const int b = blockIdx.x;
    const int tid = threadIdx.x;
    float loc[PM / 256];
    float mx = -INFINITY;
#pragma unroll
    for (int i = 0; i < PM / 256; i++) {
        loc[i] = in[(size_t)b * PM + tid + i * 256];
        mx = fmaxf(mx, loc[i]);
    }
    __shared__ float red[256];
    red[tid] = mx;
    __syncthreads();
    for (int off = 128; off > 0; off >>= 1) {
        if (tid < off) red[tid] = fmaxf(red[tid], red[tid + off]);
        __syncthreads();
    }
    mx = red[0];
    __syncthreads();
    float sum = 0.f;
#pragma unroll
    for (int i = 0; i < PM / 256; i++) {
        loc[i] = expf(loc[i] - mx);
        sum += loc[i];
    }
    red[tid] = sum;
    __syncthreads();
    for (int off = 128; off > 0; off >>= 1) {
        if (tid < off) red[tid] += red[tid + off];
        __syncthreads();
    }
    float inv = 255.0f / red[0];
#pragma unroll
    for (int i = 0; i < PM / 256; i++) {
        unsigned q = __float2uint_rn(fminf(loc[i] * inv, 255.0f));
        out[(size_t)b * PM + tid + i * 256] = (uint8_t)q;
    }
}

// comb softmax + weighted gather-read; writes read as bf16 hi/lo
__global__ __launch_bounds__(256)
void read_kernel(const float* __restrict__ vals, const int* __restrict__ idx,
                 const float* __restrict__ act, const float* __restrict__ gate,
                 const float* __restrict__ temperature, const float* __restrict__ mem,
                 __nv_bfloat16* __restrict__ rh, __nv_bfloat16* __restrict__ rl)
{
    const int b = blockIdx.x;
    const int tid = threadIdx.x;
    __shared__ float comb[PK];
    __shared__ int   sidx[PK];

    if (tid < PK) {
        const float scale = (0.5f + gate[b]) / fmaxf(temperature[0], 1e-6f);
        const int id = idx[b * PK + tid];
        sidx[tid] = id;
        float v = vals[b * PK + tid] * scale + act[(size_t)b * PM + id];
        float mx = v;
#pragma unroll
        for (int o = 16; o > 0; o >>= 1) mx = fmaxf(mx, __shfl_xor_sync(0xffffffffu, mx, o));
        float e = expf(v - mx);
        float s = e;
#pragma unroll
        for (int o = 16; o > 0; o >>= 1) s += __shfl_xor_sync(0xffffffffu, s, o);
        comb[tid] = e / s;
    }
    __syncthreads();

    for (int h = tid; h < PH; h += 256) {
        float accv = 0.f;
#pragma unroll
        for (int k = 0; k < PK; k++)
            accv += comb[k] * mem[(size_t)sidx[k] * PH + h];
        __nv_bfloat16 hh = __float2bfloat16_rn(accv);
        __nv_bfloat16 ll = __float2bfloat16_rn(accv - __bfloat162float(hh));
        rh[(size_t)b * PH + h] = hh;
        rl[(size_t)b * PH + h] = ll;
    }
}

// ===================== launch ==============================================
#define SMEM_SPLIT 81920u
#define SMEM_I8    67584u

extern "C" void kernel_launch(void* const* d_in, const int* in_sizes, int n_in,
                              void* d_out, int out_size)
{
    const float* x      = (const float*)d_in[0];
    const float* W_enc  = (const float*)d_in[2];
    const float* b_enc  = (const float*)d_in[3];
    const float* w_curv = (const float*)d_in[4];
    const float* b_curv = (const float*)d_in[5];
    const float* memsl  = (const float*)d_in[6];
    const float* assoc  = (const float*)d_in[7];
    const float* W_dec  = (const float*)d_in[8];
    const float* b_dec  = (const float*)d_in[9];
    const float* temp   = (const float*)d_in[10];
    float* out = (float*)d_out;

    float *query, *sim, *act, *gate, *vals;
    int* idxp;
    __nv_bfloat16 *xh, *xl, *qh, *ql, *rh, *rl;
    __nv_bfloat16 *wencTh, *wencTl, *wdecTh, *wdecTl, *memTh, *memTl;
    uint8_t *prob8;
    int8_t *assoc8;
    cudaGetSymbolAddress((void**)&query,  g_query);
    cudaGetSymbolAddress((void**)&sim,    g_sim);
    cudaGetSymbolAddress((void**)&act,    g_act);
    cudaGetSymbolAddress((void**)&gate,   g_gate);
    cudaGetSymbolAddress((void**)&vals,   g_vals);
    cudaGetSymbolAddress((void**)&idxp,   g_idx);
    cudaGetSymbolAddress((void**)&xh,     g_xh);
    cudaGetSymbolAddress((void**)&xl,     g_xl);
    cudaGetSymbolAddress((void**)&qh,     g_qh);
    cudaGetSymbolAddress((void**)&ql,     g_ql);
    cudaGetSymbolAddress((void**)&rh,     g_rh);
    cudaGetSymbolAddress((void**)&rl,     g_rl);
    cudaGetSymbolAddress((void**)&prob8,  g_prob8);
    cudaGetSymbolAddress((void**)&assoc8, g_assoc8);
    cudaGetSymbolAddress((void**)&wencTh, g_wencT_h);
    cudaGetSymbolAddress((void**)&wencTl, g_wencT_l);
    cudaGetSymbolAddress((void**)&wdecTh, g_wdecT_h);
    cudaGetSymbolAddress((void**)&wdecTl, g_wdecT_l);
    cudaGetSymbolAddress((void**)&memTh,  g_memT_h);
    cudaGetSymbolAddress((void**)&memTl,  g_memT_l);

    cudaFuncSetAttribute(gemm_cp<0>, cudaFuncAttributeMaxDynamicSharedMemorySize, SMEM_SPLIT);
    cudaFuncSetAttribute(gemm_cp<1>, cudaFuncAttributeMaxDynamicSharedMemorySize, SMEM_SPLIT);
    cudaFuncSetAttribute(gemm_cp<2>, cudaFuncAttributeMaxDynamicSharedMemorySize, SMEM_SPLIT);
    cudaFuncSetAttribute(gemm_i8,    cudaFuncAttributeMaxDynamicSharedMemorySize, SMEM_I8);

    // ---- prep ----
    split_kernel<<<(PB * PS * PD / 4) / 256, 256>>>(x, xh, xl);
    transpose_split_kernel<<<dim3(PH / 32, PD / 32), 256>>>(W_enc, wencTh, wencTl, PD, PH);
    split_kernel<<<(PM * PH / 4) / 256, 256>>>(memsl, memTh, memTl);
    transpose_i8_kernel<<<dim3(PM / 32, PM / 32), 256>>>(assoc, assoc8, PM, PM);
    transpose_split_kernel<<<dim3(PD / 32, PH / 32), 256>>>(W_dec, wdecTh, wdecTl, PH, PD);

    // 1. fused encoder: query = mean_S tanh(x @ W_enc + b_enc)   (bf16x3)
    gemm_cp<2><<<dim3(PH / 128, (PB * PS) / 128), 256, SMEM_SPLIT>>>(
        xh, xl, wencTh, wencTl, b_enc, nullptr, query, qh, ql, PB * PS, PH, PD);

    // 2. sim_raw = query @ mem^T (round-0 act input)              (bf16x3)
    gemm_cp<0><<<dim3(PM / 128, PB / 128), 256, SMEM_SPLIT>>>(
        qh, ql, memTh, memTl, nullptr, sim, nullptr, nullptr, nullptr, PB, PM, PH);

    // 3. gate + topk (raw sim; positive scale preserves ordering)
    gate_kernel<<<PB, 256>>>(query, w_curv, b_curv, gate);
    topk_kernel<<<PB, 256>>>(sim, vals, idxp);

    // 4. two rounds of softmax -> @assoc                          (u8 x s8 IMMA)
    softmax_kernel<<<PB, 256>>>(sim, prob8);
    gemm_i8<<<dim3(PM / 128, PB / 128), 256, SMEM_I8>>>(prob8, assoc8, act, PB, PM, PM);
    softmax_kernel<<<PB, 256>>>(act, prob8);
    gemm_i8<<<dim3(PM / 128, PB / 128), 256, SMEM_I8>>>(prob8, assoc8, act, PB, PM, PM);

    // 5. comb softmax + weighted memory read -> rh/rl
    read_kernel<<<PB, 256>>>(vals, idxp, act, gate, temp, memsl, rh, rl);

    // 6. decoder: out[b][s][:] = tanh(read @ W_dec + b_dec), broadcast fused (bf16x3)
    gemm_cp<1><<<dim3(PD / 128, PB / 128), 256, SMEM_SPLIT>>>(
        rh, rl, wdecTh, wdecTl, b_dec, out, nullptr, nullptr, nullptr, PB, PD, PH);
}

// round 10
// speedup vs baseline: 1.3103x; 1.3103x over previous
#include <cuda_runtime.h>
#include <cuda_bf16.h>
#include <cuda_fp8.h>
#include <math.h>
#include <stdint.h>

// Problem shapes (fixed per reference)
#define PB 2048
#define PS 32
#define PD 1024
#define PH 1024
#define PM 4096
#define PK 32

// ===================== low-level helpers ====================================
__device__ __forceinline__ uint32_t smem_to_u32(const void* p) {
    uint32_t a;
    asm("{ .reg .u64 t; cvta.to.shared.u64 t, %1; cvt.u32.u64 %0, t; }" : "=r"(a) : "l"(p));
    return a;
}
__device__ __forceinline__ void ldsm_x4(uint32_t* r, uint32_t addr) {
    asm volatile("ldmatrix.sync.aligned.m8n8.x4.shared.b16 {%0,%1,%2,%3}, [%4];"
                 : "=r"(r[0]), "=r"(r[1]), "=r"(r[2]), "=r"(r[3]) : "r"(addr));
}
__device__ __forceinline__ void mma_bf16(float* d, const uint32_t* a, const uint32_t* b) {
    asm volatile(
        "mma.sync.aligned.m16n8k16.row.col.f32.bf16.bf16.f32 "
        "{%0,%1,%2,%3}, {%4,%5,%6,%7}, {%8,%9}, {%0,%1,%2,%3};\n"
        : "+f"(d[0]), "+f"(d[1]), "+f"(d[2]), "+f"(d[3])
        : "r"(a[0]), "r"(a[1]), "r"(a[2]), "r"(a[3]), "r"(b[0]), "r"(b[1]));
}
__device__ __forceinline__ void mma_e4m3(float* d, const uint32_t* a, const uint32_t* b) {
    asm volatile(
        "mma.sync.aligned.m16n8k32.row.col.f32.e4m3.e4m3.f32 "
        "{%0,%1,%2,%3}, {%4,%5,%6,%7}, {%8,%9}, {%0,%1,%2,%3};\n"
        : "+f"(d[0]), "+f"(d[1]), "+f"(d[2]), "+f"(d[3])
        : "r"(a[0]), "r"(a[1]), "r"(a[2]), "r"(a[3]), "r"(b[0]), "r"(b[1]));
}
__device__ __forceinline__ void cpasync16(uint32_t s, const void* g) {
    asm volatile("cp.async.cg.shared.global [%0], [%1], 16;" :: "r"(s), "l"(g));
}
__device__ __forceinline__ void cp_commit() {
    asm volatile("cp.async.commit_group;" ::: "memory");
}

// ===================== scratch (device globals) =============================
__device__ float g_query[(size_t)PB * PH];
__device__ float g_sim[(size_t)PB * PM];
__device__ float g_act[(size_t)PB * PM];
__device__ float g_gate[PB];
__device__ float g_vals[PB * PK];
__device__ int   g_idx[PB * PK];

__device__ __nv_bfloat16 g_xh[(size_t)PB * PS * PD];
__device__ __nv_bfloat16 g_xl[(size_t)PB * PS * PD];
__device__ __nv_bfloat16 g_qh[(size_t)PB * PH];
__device__ __nv_bfloat16 g_ql[(size_t)PB * PH];
__device__ __nv_bfloat16 g_rh[(size_t)PB * PH];
__device__ __nv_bfloat16 g_rl[(size_t)PB * PH];

__device__ uint8_t g_prob8[(size_t)PB * PM];           // e4m3, prob*256
__device__ uint8_t g_assoc8[(size_t)PM * PM];          // e4m3, assoc^T*256, [N][K]

__device__ __nv_bfloat16 g_wencT_h[(size_t)PH * PD];
__device__ __nv_bfloat16 g_wencT_l[(size_t)PH * PD];
__device__ __nv_bfloat16 g_wdecT_h[(size_t)PD * PH];
__device__ __nv_bfloat16 g_wdecT_l[(size_t)PD * PH];
__device__ __nv_bfloat16 g_memT_h[(size_t)PM * PH];
__device__ __nv_bfloat16 g_memT_l[(size_t)PM * PH];

// ===================== bf16 hi/lo split helpers =============================
__device__ __forceinline__ void split4(float4 v, uint2& hi, uint2& lo) {
    __nv_bfloat16 h0 = __float2bfloat16_rn(v.x);
    __nv_bfloat16 h1 = __float2bfloat16_rn(v.y);
    __nv_bfloat16 h2 = __float2bfloat16_rn(v.z);
    __nv_bfloat16 h3 = __float2bfloat16_rn(v.w);
    __nv_bfloat16 l0 = __float2bfloat16_rn(v.x - __bfloat162float(h0));
    __nv_bfloat16 l1 = __float2bfloat16_rn(v.y - __bfloat162float(h1));
    __nv_bfloat16 l2 = __float2bfloat16_rn(v.z - __bfloat162float(h2));
    __nv_bfloat16 l3 = __float2bfloat16_rn(v.w - __bfloat162float(h3));
    hi.x = (uint32_t)__bfloat16_as_ushort(h0) | ((uint32_t)__bfloat16_as_ushort(h1) << 16);
    hi.y = (uint32_t)__bfloat16_as_ushort(h2) | ((uint32_t)__bfloat16_as_ushort(h3) << 16);
    lo.x = (uint32_t)__bfloat16_as_ushort(l0) | ((uint32_t)__bfloat16_as_ushort(l1) << 16);
    lo.y = (uint32_t)__bfloat16_as_ushort(l2) | ((uint32_t)__bfloat16_as_ushort(l3) << 16);
}
__device__ __forceinline__ uint8_t to_e4m3(float v) {
    __nv_fp8_e4m3 f(v);
    return *(uint8_t*)&f;
}

// ===================== prep kernels =========================================
// in [K][N] fp32 row-major -> out hi/lo [N][K] bf16 (transpose + split)
__global__ __launch_bounds__(256)
void transpose_split_kernel(const float* __restrict__ in, __nv_bfloat16* __restrict__ oh,
                            __nv_bfloat16* __restrict__ ol, int K, int N)
{
    __shared__ float t[32][33];
    const int tx = threadIdx.x & 31, ty = threadIdx.x >> 5;
    const int n_base = blockIdx.x * 32, k_base = blockIdx.y * 32;
#pragma unroll
    for (int j = 0; j < 4; j++) {
        int k = k_base + ty + j * 8;
        t[ty + j * 8][tx] = __ldcs(in + (size_t)k * N + n_base + tx);
    }
    __syncthreads();
#pragma unroll
    for (int j = 0; j < 4; j++) {
        int n = n_base + ty + j * 8;
        int k = k_base + tx;
        float v = t[tx][ty + j * 8];
        __nv_bfloat16 h = __float2bfloat16_rn(v);
        __nv_bfloat16 l = __float2bfloat16_rn(v - __bfloat162float(h));
        oh[(size_t)n * K + k] = h;
        ol[(size_t)n * K + k] = l;
    }
}

// in [K][N] fp32 -> out [N][K] e4m3 scaled by 256
__global__ __launch_bounds__(256)
void transpose_fp8_kernel(const float* __restrict__ in, uint8_t* __restrict__ o8,
                          int K, int N)
{
    __shared__ float t[32][33];
    const int tx = threadIdx.x & 31, ty = threadIdx.x >> 5;
    const int n_base = blockIdx.x * 32, k_base = blockIdx.y * 32;
#pragma unroll
    for (int j = 0; j < 4; j++) {
        int k = k_base + ty + j * 8;
        t[ty + j * 8][tx] = __ldcs(in + (size_t)k * N + n_base + tx);
    }
    __syncthreads();
#pragma unroll
    for (int j = 0; j < 4; j++) {
        int n = n_base + ty + j * 8;
        int k = k_base + tx;
        o8[(size_t)n * K + k] = to_e4m3(t[tx][ty + j * 8] * 256.0f);
    }
}

// elementwise fp32 -> bf16 hi/lo
__global__ __launch_bounds__(256)
void split_kernel(const float* __restrict__ in, __nv_bfloat16* __restrict__ oh,
                  __nv_bfloat16* __restrict__ ol)
{
    const size_t i = (size_t)blockIdx.x * 256 + threadIdx.x;
    float4 v = __ldcs((const float4*)in + i);
    uint2 hi, lo;
    split4(v, hi, lo);
    __stcs((uint2*)oh + i, hi);
    __stcs((uint2*)ol + i, lo);
}

// ===================== bf16 tensor-core GEMM (split3) =======================
// C[M,N] = (Ah+Al)[M,K] * (Bh+Bl)^T   all row-major bf16 [rows][K]
// Tile 128x128, BK=32, 256 thr (8 warps x 64x32), 2-stage cp.async pipeline.
// EPI 0: C fp32
// EPI 1: out[b][s][n] = tanh(c + bias[n]) broadcast over s (decoder+bcast fused)
// EPI 2: per-32-row-group mean of tanh(c+bias) -> Qf fp32 + Qh/Ql bf16
#define GPAD 80u
#define OPSZ 10240u                 // 128 rows * 80 B

template <int EPI>
__global__ __launch_bounds__(256, 2)
void gemm_cp(const __nv_bfloat16* __restrict__ Ah, const __nv_bfloat16* __restrict__ Al,
             const __nv_bfloat16* __restrict__ Bh, const __nv_bfloat16* __restrict__ Bl,
             const float* __restrict__ bias, float* __restrict__ C,
             float* __restrict__ Qf, __nv_bfloat16* __restrict__ Qh,
             __nv_bfloat16* __restrict__ Ql, int M, int N, int K)
{
    extern __shared__ char sm[];
    const uint32_t smb = smem_to_u32(sm);
    const int tid = threadIdx.x, wid = tid >> 5, lane = tid & 31;
    const int m0 = blockIdx.y * 128, n0 = blockIdx.x * 128;
    const int wm = (wid >> 2) * 64, wn = (wid & 3) * 32;
    const uint32_t offB = 2u * OPSZ;
    const uint32_t STG = 4u * OPSZ;

    float acc[4][4][4];
#pragma unroll
    for (int i = 0; i < 4; i++)
#pragma unroll
        for (int j = 0; j < 4; j++)
#pragma unroll
            for (int q = 0; q < 4; q++) acc[i][j][q] = 0.f;

    const int c_row0 = tid >> 2, c_ch0 = (tid & 3);
    const int c_row1 = (tid + 256) >> 2, c_ch1 = ((tid + 256) & 3);

    const int lr = lane & 15;
    const int kh = (lane >> 4) ? 8 : 0;
    const int br = (lane & 7) + ((lane & 16) ? 8 : 0);
    const int bk = (lane & 8) ? 8 : 0;

    const int nch = K >> 5;

#define ISSUE(cc, bb) do {                                                         \
    const int _k0 = (cc) << 5;                                                     \
    const uint32_t _sb = smb + (bb) * STG;                                         \
    cpasync16(_sb + c_row0 * GPAD + c_ch0 * 16,                                    \
              Ah + (size_t)(m0 + c_row0) * K + _k0 + c_ch0 * 8);                   \
    cpasync16(_sb + c_row1 * GPAD + c_ch1 * 16,                                    \
              Ah + (size_t)(m0 + c_row1) * K + _k0 + c_ch1 * 8);                   \
    cpasync16(_sb + offB + c_row0 * GPAD + c_ch0 * 16,                             \
              Bh + (size_t)(n0 + c_row0) * K + _k0 + c_ch0 * 8);                   \
    cpasync16(_sb + offB + c_row1 * GPAD + c_ch1 * 16,                             \
              Bh + (size_t)(n0 + c_row1) * K + _k0 + c_ch1 * 8);                   \
    cpasync16(_sb + OPSZ + c_row0 * GPAD + c_ch0 * 16,                             \
              Al + (size_t)(m0 + c_row0) * K + _k0 + c_ch0 * 8);                   \
    cpasync16(_sb + OPSZ + c_row1 * GPAD + c_ch1 * 16,                             \
              Al + (size_t)(m0 + c_row1) * K + _k0 + c_ch1 * 8);                   \
    cpasync16(_sb + 3u * OPSZ + c_row0 * GPAD + c_ch0 * 16,                        \
              Bl + (size_t)(n0 + c_row0) * K + _k0 + c_ch0 * 8);                   \
    cpasync16(_sb + 3u * OPSZ + c_row1 * GPAD + c_ch1 * 16,                        \
              Bl + (size_t)(n0 + c_row1) * K + _k0 + c_ch1 * 8);                   \
    cp_commit();                                                                   \
} while (0)

    ISSUE(0, 0);

    for (int c = 0; c < nch; c++) {
        const int buf = c & 1;
        if (c + 1 < nch) {
            ISSUE(c + 1, buf ^ 1);
            asm volatile("cp.async.wait_group 1;" ::: "memory");
        } else {
            asm volatile("cp.async.wait_group 0;" ::: "memory");
        }
        __syncthreads();

        const uint32_t sb = smb + buf * STG;
#pragma unroll
        for (int ks = 0; ks < 2; ks++) {
            uint32_t ah[4][4], bhf[2][4];
#pragma unroll
            for (int mt = 0; mt < 4; mt++)
                ldsm_x4(ah[mt], sb + (wm + mt * 16 + lr) * GPAD + (ks * 16 + kh) * 2);
#pragma unroll
            for (int p = 0; p < 2; p++)
                ldsm_x4(bhf[p], sb + offB + (wn + p * 16 + br) * GPAD + (ks * 16 + bk) * 2);
#pragma unroll
            for (int mt = 0; mt < 4; mt++)
#pragma unroll
                for (int nt = 0; nt < 4; nt++)
                    mma_bf16(acc[mt][nt], ah[mt], &bhf[nt >> 1][(nt & 1) * 2]);
            {
                uint32_t al[4][4];
#pragma unroll
                for (int mt = 0; mt < 4; mt++)
                    ldsm_x4(al[mt], sb + OPSZ + (wm + mt * 16 + lr) * GPAD + (ks * 16 + kh) * 2);
#pragma unroll
                for (int mt = 0; mt < 4; mt++)
#pragma unroll
                    for (int nt = 0; nt < 4; nt++)
                        mma_bf16(acc[mt][nt], al[mt], &bhf[nt >> 1][(nt & 1) * 2]);
                uint32_t blf[2][4];
#pragma unroll
                for (int p = 0; p < 2; p++)
                    ldsm_x4(blf[p], sb + 3u * OPSZ + (wn + p * 16 + br) * GPAD + (ks * 16 + bk) * 2);
#pragma unroll
                for (int mt = 0; mt < 4; mt++)
#pragma unroll
                    for (int nt = 0; nt < 4; nt++)
                        mma_bf16(acc[mt][nt], ah[mt], &blf[nt >> 1][(nt & 1) * 2]);
            }
        }
        __syncthreads();
    }
#undef ISSUE

    // -------- epilogue: regs -> smem (padded) -> gmem -----------------------
    float* smf = (float*)sm;   // 128 x 132 floats = 67584 B
#pragma unroll
    for (int mt = 0; mt < 4; mt++) {
#pragma unroll
        for (int nt = 0; nt < 4; nt++) {
            int r = wm + mt * 16 + (lane >> 2);
            int cc = wn + nt * 8 + (lane & 3) * 2;
            float v0 = acc[mt][nt][0], v1 = acc[mt][nt][1];
            float v2 = acc[mt][nt][2], v3 = acc[mt][nt][3];
            if (EPI >= 1) {
                float b0 = bias[n0 + cc], b1 = bias[n0 + cc + 1];
                v0 = tanhf(v0 + b0); v1 = tanhf(v1 + b1);
                v2 = tanhf(v2 + b0); v3 = tanhf(v3 + b1);
            }
            smf[r * 132 + cc] = v0;
            smf[r * 132 + cc + 1] = v1;
            smf[(r + 8) * 132 + cc] = v2;
            smf[(r + 8) * 132 + cc + 1] = v3;
        }
    }
    __syncthreads();

    if (EPI == 2) {
#pragma unroll
        for (int i = 0; i < 2; i++) {
            int task = tid + i * 256;           // 512: 4 groups x 128 cols
            int grp = task >> 7, col = task & 127;
            float s = 0.f;
#pragma unroll
            for (int rr = 0; rr < 32; rr++) s += smf[(grp * 32 + rr) * 132 + col];
            s *= (1.0f / 32.0f);
            size_t qi = (size_t)(blockIdx.y * 4 + grp) * N + n0 + col;
            Qf[qi] = s;
            __nv_bfloat16 h = __float2bfloat16_rn(s);
            __nv_bfloat16 l = __float2bfloat16_rn(s - __bfloat162float(h));
            Qh[qi] = h;
            Ql[qi] = l;
        }
    } else if (EPI == 1) {
        // decoder + broadcast: row = batch b; write out[b][s][:] for all s
#pragma unroll
        for (int i = 0; i < 16; i++) {
            int id = tid + i * 256;
            int row = id >> 5, c4 = id & 31;
            float4 o;
            o.x = smf[row * 132 + c4 * 4 + 0];
            o.y = smf[row * 132 + c4 * 4 + 1];
            o.z = smf[row * 132 + c4 * 4 + 2];
            o.w = smf[row * 132 + c4 * 4 + 3];
            float* base = C + ((size_t)(m0 + row) * PS) * PD + n0 + c4 * 4;
#pragma unroll 4
            for (int s = 0; s < PS; s++)
                __stcs((float4*)(base + (size_t)s * PD), o);
        }
    } else {
#pragma unroll
        for (int i = 0; i < 16; i++) {
            int id = tid + i * 256;
            int row = id >> 5, c4 = id & 31;
            float4 o;
            o.x = smf[row * 132 + c4 * 4 + 0];
            o.y = smf[row * 132 + c4 * 4 + 1];
            o.z = smf[row * 132 + c4 * 4 + 2];
            o.w = smf[row * 132 + c4 * 4 + 3];
            *(float4*)(C + (size_t)(m0 + row) * N + n0 + c4 * 4) = o;
        }
    }
}

// ===================== fp8 tensor-core GEMM (assoc) =========================
// C[M,N] = (A*256)[M,K]e4m3 * ((B*256)[N][K]e4m3)^T * 2^-16
// Tile 128x128, BK=64 bytes, 2-stage cp.async, m16n8k32 e4m3 MMA.
__global__ __launch_bounds__(256, 2)
void gemm_fp8(const uint8_t* __restrict__ A, const uint8_t* __restrict__ B,
              float* __restrict__ C, int M, int N, int K)
{
    extern __shared__ char sm[];
    const uint32_t smb = smem_to_u32(sm);
    const int tid = threadIdx.x, wid = tid >> 5, lane = tid & 31;
    const int m0 = blockIdx.y * 128, n0 = blockIdx.x * 128;
    const int wm = (wid >> 2) * 64, wn = (wid & 3) * 32;
    const uint32_t offB = OPSZ;
    const uint32_t STG = 2u * OPSZ;

    float acc[4][4][4];
#pragma unroll
    for (int i = 0; i < 4; i++)
#pragma unroll
        for (int j = 0; j < 4; j++)
#pragma unroll
            for (int q = 0; q < 4; q++) acc[i][j][q] = 0.f;

    const int c_row0 = tid >> 2, c_ch0 = (tid & 3);
    const int c_row1 = (tid + 256) >> 2, c_ch1 = ((tid + 256) & 3);

    const int lr = lane & 15;
    const int khb = (lane >> 4) ? 16 : 0;                 // byte offset within 32B k-step
    const int br = (lane & 7) + ((lane & 16) ? 8 : 0);
    const int bkb = (lane & 8) ? 16 : 0;

    const int nch = K >> 6;                               // 64 fp8 per chunk

#define ISSUE8(cc, bb) do {                                                        \
    const int _k0 = (cc) << 6;                                                     \
    const uint32_t _sb = smb + (bb) * STG;                                         \
    cpasync16(_sb + c_row0 * GPAD + c_ch0 * 16,                                    \
              A + (size_t)(m0 + c_row0) * K + _k0 + c_ch0 * 16);                   \
    cpasync16(_sb + c_row1 * GPAD + c_ch1 * 16,                                    \
              A + (size_t)(m0 + c_row1) * K + _k0 + c_ch1 * 16);                   \
    cpasync16(_sb + offB + c_row0 * GPAD + c_ch0 * 16,                             \
              B + (size_t)(n0 + c_row0) * K + _k0 + c_ch0 * 16);                   \
    cpasync16(_sb + offB + c_row1 * GPAD + c_ch1 * 16,                             \
              B + (size_t)(n0 + c_row1) * K + _k0 + c_ch1 * 16);                   \
    cp_commit();                                                                   \
} while (0)

    ISSUE8(0, 0);

    for (int c = 0; c < nch; c++) {
        const int buf = c & 1;
        if (c + 1 < nch) {
            ISSUE8(c + 1, buf ^ 1);
            asm volatile("cp.async.wait_group 1;" ::: "memory");
        } else {
            asm volatile("cp.async.wait_group 0;" ::: "memory");
        }
        __syncthreads();

        const uint32_t sb = smb + buf * STG;
#pragma unroll
        for (int ks = 0; ks < 2; ks++) {                  // 2 x 32-byte k-steps
            uint32_t ah[4][4], bhf[2][4];
#pragma unroll
            for (int mt = 0; mt < 4; mt++)
                ldsm_x4(ah[mt], sb + (wm + mt * 16 + lr) * GPAD + ks * 32 + khb);
#pragma unroll
            for (int p = 0; p < 2; p++)
                ldsm_x4(bhf[p], sb + offB + (wn + p * 16 + br) * GPAD + ks * 32 + bkb);
#pragma unroll
            for (int mt = 0; mt < 4; mt++)
#pragma unroll
                for (int nt = 0; nt < 4; nt++)
                    mma_e4m3(acc[mt][nt], ah[mt], &bhf[nt >> 1][(nt & 1) * 2]);
        }
        __syncthreads();
    }
#undef ISSUE8

    // epilogue with 2^-16 descale
    float* smf = (float*)sm;
    const float DS = 1.0f / 65536.0f;
#pragma unroll
    for (int mt = 0; mt < 4; mt++) {
#pragma unroll
        for (int nt = 0; nt < 4; nt++) {
            int r = wm + mt * 16 + (lane >> 2);
            int cc = wn + nt * 8 + (lane & 3) * 2;
            smf[r * 132 + cc]           = acc[mt][nt][0] * DS;
            smf[r * 132 + cc + 1]       = acc[mt][nt][1] * DS;
            smf[(r + 8) * 132 + cc]     = acc[mt][nt][2] * DS;
            smf[(r + 8) * 132 + cc + 1] = acc[mt][nt][3] * DS;
        }
    }
    __syncthreads();
#pragma unroll
    for (int i = 0; i < 16; i++) {
        int id = tid + i * 256;
        int row = id >> 5, c4 = id & 31;
        float4 o;
        o.x = smf[row * 132 + c4 * 4 + 0];
        o.y = smf[row * 132 + c4 * 4 + 1];
        o.z = smf[row * 132 + c4 * 4 + 2];
        o.w = smf[row * 132 + c4 * 4 + 3];
        *(float4*)(C + (size_t)(m0 + row) * N + n0 + c4 * 4) = o;
    }
}

// ===================== small kernels =======================================
__global__ __launch_bounds__(256)
void gate_kernel(const float* __restrict__ query, const float* __restrict__ w_curv,
                 const float* __restrict__ b_curv, float* __restrict__ gate)
{
    const int b = blockIdx.x;
    const int tid = threadIdx.x;
    float s = 0.f;
    for (int h = tid; h < PH; h += 256) s += query[(size_t)b * PH + h] * w_curv[h];
    __shared__ float red[256];
    red[tid] = s;
    __syncthreads();
    for (int off = 128; off > 0; off >>= 1) {
        if (tid < off) red[tid] += red[tid + off];
        __syncthreads();
    }
    if (tid == 0) {
        float z = red[0] + b_curv[0];
        gate[b] = 1.f / (1.f + expf(-z));
    }
}

// register-resident iterative top-32
__global__ __launch_bounds__(256)
void topk_kernel(const float* __restrict__ sim, float* __restrict__ vals,
                 int* __restrict__ idx)
{
    const int b = blockIdx.x, tid = threadIdx.x, lane = tid & 31, wid = tid >> 5;
    const float* row = sim + (size_t)b * PM;
    float v[16];
#pragma unroll
    for (int i = 0; i < 16; i++) v[i] = row[tid + i * 256];
    float lm = -INFINITY; int ls = 0;
#pragma unroll
    for (int i = 0; i < 16; i++) if (v[i] > lm) { lm = v[i]; ls = i; }

    __shared__ float swv[8];
    __shared__ int   swi[8];
    __shared__ int   sbest;

    for (int k = 0; k < PK; k++) {
        float m = lm; int mi = ls * 256 + tid;
#pragma unroll
        for (int o = 16; o > 0; o >>= 1) {
            float ov = __shfl_xor_sync(0xffffffffu, m, o);
            int   oi = __shfl_xor_sync(0xffffffffu, mi, o);
            if (ov > m || (ov == m && oi < mi)) { m = ov; mi = oi; }
        }
        if (lane == 0) { swv[wid] = m; swi[wid] = mi; }
        __syncthreads();
        if (tid == 0) {
            float bv = swv[0]; int bi = swi[0];
#pragma unroll
            for (int w = 1; w < 8; w++)
                if (swv[w] > bv || (swv[w] == bv && swi[w] < bi)) { bv = swv[w]; bi = swi[w]; }
            vals[b * PK + k] = bv;
            idx[b * PK + k]  = bi;
            sbest = bi;
        }
        __syncthreads();
        const int bi = sbest;
        if ((bi & 255) == tid) {
            const int slot = bi >> 8;
#pragma unroll
            for (int i = 0; i < 16; i++) if (i == slot) v[i] = -INFINITY;
            lm = -INFINITY; ls = 0;
#pragma unroll
            for (int i = 0; i < 16; i++) if (v[i] > lm) { lm = v[i]; ls = i; }
        }
    }
}

// row softmax over M=4096, writes e4m3 scaled by 256 (MMA-ready A operand)
__global__ __launch_bounds__(256)
void softmax_kernel(const float* __restrict__ in, uint8_t* __restrict__ out)
{
    const int b = blockIdx.x;
    const int tid = threadIdx.x;
    float loc[PM / 256];
    float mx = -INFINITY;
#pragma unroll
    for (int i = 0; i < PM / 256; i++) {
        loc[i] = in[(size_t)b * PM + tid + i * 256];
        mx = fmaxf(mx, loc[i]);
    }
    __shared__ float red[256];
    red[tid] = mx;
    __syncthreads();
    for (int off = 128; off > 0; off >>= 1) {
        if (tid < off) red[tid] = fmaxf(red[tid], red[tid + off]);
        __syncthreads();
    }
    mx = red[0];
    __syncthreads();
    float sum = 0.f;
#pragma unroll
    for (int i = 0; i < PM / 256; i++) {
        loc[i] = expf(loc[i] - mx);
        sum += loc[i];
    }
    red[tid] = sum;
    __syncthreads();
    for (int off = 128; off > 0; off >>= 1) {
        if (tid < off) red[tid] += red[tid + off];
        __syncthreads();
    }
    float inv = 256.0f / red[0];
#pragma unroll
    for (int i = 0; i < PM / 256; i++)
        out[(size_t)b * PM + tid + i * 256] = to_e4m3(loc[i] * inv);
}

// comb softmax + weighted gather-read; writes read as bf16 hi/lo
__global__ __launch_bounds__(256)
void read_kernel(const float* __restrict__ vals, const int* __restrict__ idx,
                 const float* __restrict__ act, const float* __restrict__ gate,
                 const float* __restrict__ temperature, const float* __restrict__ mem,
                 __nv_bfloat16* __restrict__ rh, __nv_bfloat16* __restrict__ rl)
{
    const int b = blockIdx.x;
    const int tid = threadIdx.x;
    __shared__ float comb[PK];
    __shared__ int   sidx[PK];

    if (tid < PK) {
        const float scale = (0.5f + gate[b]) / fmaxf(temperature[0], 1e-6f);
        const int id = idx[b * PK + tid];
        sidx[tid] = id;
        float v = vals[b * PK + tid] * scale + act[(size_t)b * PM + id];
        float mx = v;
#pragma unroll
        for (int o = 16; o > 0; o >>= 1) mx = fmaxf(mx, __shfl_xor_sync(0xffffffffu, mx, o));
        float e = expf(v - mx);
        float s = e;
#pragma unroll
        for (int o = 16; o > 0; o >>= 1) s += __shfl_xor_sync(0xffffffffu, s, o);
        comb[tid] = e / s;
    }
    __syncthreads();

    for (int h = tid; h < PH; h += 256) {
        float accv = 0.f;
#pragma unroll
        for (int k = 0; k < PK; k++)
            accv += comb[k] * mem[(size_t)sidx[k] * PH + h];
        __nv_bfloat16 hh = __float2bfloat16_rn(accv);
        __nv_bfloat16 ll = __float2bfloat16_rn(accv - __bfloat162float(hh));
        rh[(size_t)b * PH + h] = hh;
        rl[(size_t)b * PH + h] = ll;
    }
}

// ===================== launch ==============================================
#define SMEM_SPLIT 81920u
#define SMEM_F8    67584u

extern "C" void kernel_launch(void* const* d_in, const int* in_sizes, int n_in,
                              void* d_out, int out_size)
{
    const float* x      = (const float*)d_in[0];
    const float* W_enc  = (const float*)d_in[2];
    const float* b_enc  = (const float*)d_in[3];
    const float* w_curv = (const float*)d_in[4];
    const float* b_curv = (const float*)d_in[5];
    const float* memsl  = (const float*)d_in[6];
    const float* assoc  = (const float*)d_in[7];
    const float* W_dec  = (const float*)d_in[8];
    const float* b_dec  = (const float*)d_in[9];
    const float* temp   = (const float*)d_in[10];
    float* out = (float*)d_out;

    float *query, *sim, *act, *gate, *vals;
    int* idxp;
    __nv_bfloat16 *xh, *xl, *qh, *ql, *rh, *rl;
    __nv_bfloat16 *wencTh, *wencTl, *wdecTh, *wdecTl, *memTh, *memTl;
    uint8_t *prob8, *assoc8;
    cudaGetSymbolAddress((void**)&query,  g_query);
    cudaGetSymbolAddress((void**)&sim,    g_sim);
    cudaGetSymbolAddress((void**)&act,    g_act);
    cudaGetSymbolAddress((void**)&gate,   g_gate);
    cudaGetSymbolAddress((void**)&vals,   g_vals);
    cudaGetSymbolAddress((void**)&idxp,   g_idx);
    cudaGetSymbolAddress((void**)&xh,     g_xh);
    cudaGetSymbolAddress((void**)&xl,     g_xl);
    cudaGetSymbolAddress((void**)&qh,     g_qh);
    cudaGetSymbolAddress((void**)&ql,     g_ql);
    cudaGetSymbolAddress((void**)&rh,     g_rh);
    cudaGetSymbolAddress((void**)&rl,     g_rl);
    cudaGetSymbolAddress((void**)&prob8,  g_prob8);
    cudaGetSymbolAddress((void**)&assoc8, g_assoc8);
    cudaGetSymbolAddress((void**)&wencTh, g_wencT_h);
    cudaGetSymbolAddress((void**)&wencTl, g_wencT_l);
    cudaGetSymbolAddress((void**)&wdecTh, g_wdecT_h);
    cudaGetSymbolAddress((void**)&wdecTl, g_wdecT_l);
    cudaGetSymbolAddress((void**)&memTh,  g_memT_h);
    cudaGetSymbolAddress((void**)&memTl,  g_memT_l);

    cudaFuncSetAttribute(gemm_cp<0>, cudaFuncAttributeMaxDynamicSharedMemorySize, SMEM_SPLIT);
    cudaFuncSetAttribute(gemm_cp<1>, cudaFuncAttributeMaxDynamicSharedMemorySize, SMEM_SPLIT);
    cudaFuncSetAttribute(gemm_cp<2>, cudaFuncAttributeMaxDynamicSharedMemorySize, SMEM_SPLIT);
    cudaFuncSetAttribute(gemm_fp8,   cudaFuncAttributeMaxDynamicSharedMemorySize, SMEM_F8);

    // ---- prep ----
    split_kernel<<<(PB * PS * PD / 4) / 256, 256>>>(x, xh, xl);
    transpose_split_kernel<<<dim3(PH / 32, PD / 32), 256>>>(W_enc, wencTh, wencTl, PD, PH);
    split_kernel<<<(PM * PH / 4) / 256, 256>>>(memsl, memTh, memTl);
    transpose_fp8_kernel<<<dim3(PM / 32, PM / 32), 256>>>(assoc, assoc8, PM, PM);
    transpose_split_kernel<<<dim3(PD / 32, PH / 32), 256>>>(W_dec, wdecTh, wdecTl, PH, PD);

    // 1. fused encoder: query = mean_S tanh(x @ W_enc + b_enc)   (bf16x3)
    gemm_cp<2><<<dim3(PH / 128, (PB * PS) / 128), 256, SMEM_SPLIT>>>(
        xh, xl, wencTh, wencTl, b_enc, nullptr, query, qh, ql, PB * PS, PH, PD);

    // 2. sim_raw = query @ mem^T (round-0 act input)              (bf16x3)
    gemm_cp<0><<<dim3(PM / 128, PB / 128), 256, SMEM_SPLIT>>>(
        qh, ql, memTh, memTl, nullptr, sim, nullptr, nullptr, nullptr, PB, PM, PH);

    // 3. gate + topk (raw sim; positive scale preserves ordering)
    gate_kernel<<<PB, 256>>>(query, w_curv, b_curv, gate);
    topk_kernel<<<PB, 256>>>(sim, vals, idxp);

    // 4. two rounds of softmax -> @assoc                          (e4m3 fp8)
    softmax_kernel<<<PB, 256>>>(sim, prob8);
    gemm_fp8<<<dim3(PM / 128, PB / 128), 256, SMEM_F8>>>(prob8, assoc8, act, PB, PM, PM);
    softmax_kernel<<<PB, 256>>>(act, prob8);
    gemm_fp8<<<dim3(PM / 128, PB / 128), 256, SMEM_F8>>>(prob8, assoc8, act, PB, PM, PM);

    // 5. comb softmax + weighted memory read -> rh/rl
    read_kernel<<<PB, 256>>>(vals, idxp, act, gate, temp, memsl, rh, rl);

    // 6. decoder: out[b][s][:] = tanh(read @ W_dec + b_dec), broadcast fused (bf16x3)
    gemm_cp<1><<<dim3(PD / 128, PB / 128), 256, SMEM_SPLIT>>>(
        rh, rl, wdecTh, wdecTl, b_dec, out, nullptr, nullptr, nullptr, PB, PD, PH);
}